// round 5
// baseline (speedup 1.0000x reference)
#include <cuda_runtime.h>

// out[e,b,o] = sum_n x[e,b,n] * W[e,o,n] + b[e,o]
// E=50000, B=512, N=O=2. Pure HBM stream: 410 MB compulsory traffic.
//
// R4: EPB 4 -> 8. The eight x float4 loads (the DRAM stream) are batched
// up front per thread (MLP_p1 = 8); W/b param loads (L2-resident, uniform
// per block) are folded into the compute loop to keep regs ~60 instead of
// ~90, preserving ~50% occupancy. Grid-stride + tail keeps correctness for
// any E.
//
//   x   (E,B,2) fp32 -> float4 = 2 batch rows : x4[e*256 + t]
//   out (E,B,2) fp32 -> same                  : out4[e*256 + t]
//   W   (E,2,2) fp32 -> float4 per edge       : W4[e]
//   b   (E,2)   fp32 -> float2 per edge       : b2[e]

static constexpr int B_HALF = 256;  // 512 batch rows / 2 per thread
static constexpr int EPB    = 8;    // edges per block-iteration

__global__ __launch_bounds__(256) void per_edge_linear_kernel(
    const float4* __restrict__ x4,
    const float4* __restrict__ W4,
    const float2* __restrict__ b2,
    float4* __restrict__ out4,
    int E)
{
    const int t = threadIdx.x;
    const int num_groups = (E + EPB - 1) / EPB;

    for (int grp = blockIdx.x; grp < num_groups; grp += gridDim.x) {
        const int e0 = grp * EPB;

        if (e0 + EPB <= E) {
            // 8 independent 128-bit streaming loads, batched front.
            float4 xv[EPB];
            #pragma unroll
            for (int g = 0; g < EPB; ++g)
                xv[g] = x4[(e0 + g) * B_HALF + t];

            // Params are uniform per block and L2-resident; load lazily to
            // cap register pressure. ptxas may hoist some — that's fine.
            #pragma unroll
            for (int g = 0; g < EPB; ++g) {
                const float4 w  = __ldg(&W4[e0 + g]);
                const float2 bb = __ldg(&b2[e0 + g]);
                float4 o;
                o.x = fmaf(xv[g].x, w.x, fmaf(xv[g].y, w.y, bb.x));
                o.y = fmaf(xv[g].x, w.z, fmaf(xv[g].y, w.w, bb.y));
                o.z = fmaf(xv[g].z, w.x, fmaf(xv[g].w, w.y, bb.x));
                o.w = fmaf(xv[g].z, w.z, fmaf(xv[g].w, w.w, bb.y));
                out4[(e0 + g) * B_HALF + t] = o;
            }
        } else {
            // Tail group (only if E % EPB != 0).
            for (int e = e0; e < E; ++e) {
                const float4 w  = __ldg(&W4[e]);
                const float2 bb = __ldg(&b2[e]);
                const float4 xv = x4[e * B_HALF + t];
                float4 o;
                o.x = fmaf(xv.x, w.x, fmaf(xv.y, w.y, bb.x));
                o.y = fmaf(xv.x, w.z, fmaf(xv.y, w.w, bb.y));
                o.z = fmaf(xv.z, w.x, fmaf(xv.w, w.y, bb.x));
                o.w = fmaf(xv.z, w.z, fmaf(xv.w, w.w, bb.y));
                out4[e * B_HALF + t] = o;
            }
        }
    }
}

extern "C" void kernel_launch(void* const* d_in, const int* in_sizes, int n_in,
                              void* d_out, int out_size)
{
    const float4* x4 = (const float4*)d_in[0];   // x (E,B,N) fp32
    const float4* W4 = (const float4*)d_in[1];   // W (E,O,N) fp32
    const float2* b2 = (const float2*)d_in[2];   // b (E,O)   fp32
    float4* out4     = (float4*)d_out;           // out (E,B,O) fp32

    const int E = in_sizes[1] / 4;               // W has E*O*N = E*4 elements
    int grid = (E + EPB - 1) / EPB;

    per_edge_linear_kernel<<<grid, 256>>>(x4, W4, b2, out4, E);
}